// round 13
// baseline (speedup 1.0000x reference)
#include <cuda_runtime.h>
#include <cuda_bf16.h>

// Problem constants
#define D        256
#define DD       65536
#define BATCH    4096
#define T        100
#define DT_STEP  0.05f
#define NPOW     10          // z_k terms k=1..10; tail (1.6)^11/11! ~ 4e-7

typedef unsigned int u32;
typedef unsigned long long u64t;

// ---------------------------------------------------------------------------
// Device scratch (static globals; no allocation anywhere)
// ---------------------------------------------------------------------------
__device__ float          g_W[12ull * DD];              // B^k, k=1..10 (slot 0 unused)
__device__ __nv_bfloat16  g_Whi[(size_t)NPOW * DD];     // bf16 hi of B^k (slot k-1)
__device__ __nv_bfloat16  g_Wlo[(size_t)NPOW * DD];     // bf16 lo
__device__ __nv_bfloat16  g_Xhi[(size_t)BATCH * D];
__device__ __nv_bfloat16  g_Xlo[(size_t)BATCH * D];
__device__ float          g_Z[(size_t)NPOW * BATCH * D]; // z_k = x*(B^T)^k (slot k-1)
__device__ u32            g_cnt[8];                      // grid-barrier counters (memset per run)

// ---------------------------------------------------------------------------
// PTX helpers (baseline ISA only — compute_103-safe)
// ---------------------------------------------------------------------------
__device__ __forceinline__ u32 smem_u32(const void* p) {
    u32 a;
    asm("{ .reg .u64 t; cvta.to.shared.u64 t, %1; cvt.u32.u64 %0, t; }" : "=r"(a) : "l"(p));
    return a;
}
__device__ __forceinline__ void cpa16(u32 dst, const void* src) {
    asm volatile("cp.async.cg.shared.global [%0], [%1], 16;" :: "r"(dst), "l"(src) : "memory");
}
__device__ __forceinline__ void cpa_commit() { asm volatile("cp.async.commit_group;" ::: "memory"); }
template <int N>
__device__ __forceinline__ void cpa_wait() {
    asm volatile("cp.async.wait_group %0;" :: "n"(N) : "memory");
}
__device__ __forceinline__ void ldm4(u32* r, u32 a) {
    asm volatile("ldmatrix.sync.aligned.m8n8.x4.shared.b16 {%0,%1,%2,%3}, [%4];"
                 : "=r"(r[0]), "=r"(r[1]), "=r"(r[2]), "=r"(r[3]) : "r"(a));
}
__device__ __forceinline__ void mma16816(float* c, const u32* a, u32 b0, u32 b1) {
    asm volatile("mma.sync.aligned.m16n8k16.row.col.f32.bf16.bf16.f32 "
                 "{%0,%1,%2,%3}, {%4,%5,%6,%7}, {%8,%9}, {%0,%1,%2,%3};"
                 : "+f"(c[0]), "+f"(c[1]), "+f"(c[2]), "+f"(c[3])
                 : "r"(a[0]), "r"(a[1]), "r"(a[2]), "r"(a[3]), "r"(b0), "r"(b1));
}
__device__ __forceinline__ u64t pack_dup(float v) {
    u64t r;
    asm("mov.b64 %0, {%1, %1};" : "=l"(r) : "f"(v));
    return r;
}
__device__ __forceinline__ void fma2(u64t& d, u64t a, u64t b) {
    asm("fma.rn.f32x2 %0, %1, %2, %0;" : "+l"(d) : "l"(a), "l"(b));
}
__device__ __forceinline__ u64t mul2(u64t a, u64t b) {
    u64t r;
    asm("mul.rn.f32x2 %0, %1, %2;" : "=l"(r) : "l"(a), "l"(b));
    return r;
}

#define SWZ(o) ((o) ^ (((o) >> 3) & 0x70))

// ---------------------------------------------------------------------------
// Software grid barrier: monotonic counter per phase (idx), release+acquire.
// All 128 CTAs guaranteed co-resident (128 < 148 SMs).
// ---------------------------------------------------------------------------
__device__ __forceinline__ void gridbar(int idx, u32 n) {
    __syncthreads();
    if (threadIdx.x == 0) {
        __threadfence();                       // release prior stores GPU-wide
        atomicAdd(&g_cnt[idx], 1u);
        u32 v;
        do {
            asm volatile("ld.global.acquire.gpu.u32 %0, [%1];"
                         : "=r"(v) : "l"(&g_cnt[idx]) : "memory");
        } while (v < n);
    }
    __syncthreads();
}

// ---------------------------------------------------------------------------
// 32x32 tile of a 256x256x256 fp32 matmul: C_tile = X @ Y  (proven body)
// tileIdx in 0..63: row = tileIdx>>3, col = tileIdx&7.
// ---------------------------------------------------------------------------
__device__ void mm_tile(const float* __restrict__ X,
                        const float* __restrict__ Y,
                        float* __restrict__ C, int tileIdx)
{
    __shared__ float Xs[32][34];
    __shared__ float Ys[32][32];

    const int rowBase = (tileIdx >> 3) * 32;
    const int colBase = (tileIdx & 7) * 32;

    const int tid = threadIdx.x;
    const int lrow = tid >> 3;
    const int lq   = (tid & 7) * 4;
    const int tx = tid & 15;
    const int ty = tid >> 4;

    const float* xPtr = X + (size_t)(rowBase + lrow) * D + lq;
    const float* yPtr = Y + (size_t)lrow * D + colBase + lq;

    float4 xv = *(const float4*)xPtr;
    float4 yv = *(const float4*)yPtr;

    float a00 = 0.f, a01 = 0.f, a10 = 0.f, a11 = 0.f;

    for (int d0 = 0; d0 < D; d0 += 32) {
        __syncthreads();
        Xs[lq + 0][lrow] = xv.x; Xs[lq + 1][lrow] = xv.y;
        Xs[lq + 2][lrow] = xv.z; Xs[lq + 3][lrow] = xv.w;
        *(float4*)&Ys[lrow][lq] = yv;
        __syncthreads();

        if (d0 + 32 < D) {
            xv = *(const float4*)(xPtr + d0 + 32);
            yv = *(const float4*)(yPtr + (size_t)(d0 + 32) * D);
        }

#pragma unroll
        for (int kk = 0; kk < 32; ++kk) {
            float2 a = *(const float2*)&Xs[kk][ty * 2];
            float2 b = *(const float2*)&Ys[kk][tx * 2];
            a00 += a.x * b.x; a01 += a.x * b.y;
            a10 += a.y * b.x; a11 += a.y * b.y;
        }
    }

    int gr = rowBase + ty * 2;
    int gc = colBase + tx * 2;
    float2 v0; v0.x = a00; v0.y = a01;
    float2 v1; v1.x = a10; v1.y = a11;
    *(float2*)&C[(size_t)gr * D + gc] = v0;
    *(float2*)&C[(size_t)(gr + 1) * D + gc] = v1;
}

// ---------------------------------------------------------------------------
// prep: ONE persistent kernel (128 CTAs) = B build + full power chain +
// all bf16 splits. Phases separated by software grid barriers.
//   ph0: W1 = B = A + I
//   ph1: W2 = W1*W1                         (64 tiles)
//   ph2: W3 = W2*W1 ; W4 = W2*W2            (128 tiles)
//   ph3: W5..W8 = W4*{W1..W4}               (256 tiles, 2/CTA)
//   ph4: W9 = W8*W1 ; W10 = W8*W2           (128 tiles)
//   ph5: bf16 hi/lo splits of W1..W10 and X0
// ---------------------------------------------------------------------------
#define WPD(k) (g_W + (size_t)(k) * DD)

__global__ void __launch_bounds__(256)
prep_kernel(const float* __restrict__ A, const float* __restrict__ X0)
{
    const int tid = threadIdx.x;
    const int cta = blockIdx.x;

    // ---- phase 0: B = A + I ----
#pragma unroll
    for (int j = 0; j < 2; ++j) {
        int e = cta * 512 + j * 256 + tid;
        int r = e >> 8, c = e & 255;
        g_W[DD + e] = A[e] + ((r == c) ? 1.0f : 0.0f);
    }
    gridbar(0, 128);

    // ---- phase 1 ----
    if (cta < 64) mm_tile(WPD(1), WPD(1), WPD(2), cta);
    gridbar(1, 128);

    // ---- phase 2 ----
    if (cta < 64) mm_tile(WPD(2), WPD(1), WPD(3), cta);
    else          mm_tile(WPD(2), WPD(2), WPD(4), cta - 64);
    gridbar(2, 128);

    // ---- phase 3: 256 tiles, 2 per CTA ----
#pragma unroll
    for (int q = 0; q < 2; ++q) {
        int tt = cta * 2 + q;          // 0..255
        int m = tt >> 6;               // 0..3
        mm_tile(WPD(4), WPD(1 + m), WPD(5 + m), tt & 63);
    }
    gridbar(3, 128);

    // ---- phase 4 ----
    if (cta < 64) mm_tile(WPD(8), WPD(1), WPD(9), cta);
    else          mm_tile(WPD(8), WPD(2), WPD(10), cta - 64);
    gridbar(4, 128);

    // ---- phase 5: splits ----
    // W1..W10 -> g_Whi/g_Wlo: NPOW*DD = 655360 floats; 5 float4 per thread
#pragma unroll
    for (int it = 0; it < 5; ++it) {
        size_t e = (size_t)cta * 5120 + (size_t)it * 1024 + (size_t)tid * 4;
        float4 v = *(const float4*)(g_W + DD + e);
        float xs[4] = {v.x, v.y, v.z, v.w};
#pragma unroll
        for (int j = 0; j < 4; ++j) {
            __nv_bfloat16 h = __float2bfloat16(xs[j]);
            g_Whi[e + j] = h;
            g_Wlo[e + j] = __float2bfloat16(xs[j] - __bfloat162float(h));
        }
    }
    // X0 -> g_Xhi/g_Xlo: 1048576 floats; 8 float4 per thread
#pragma unroll
    for (int it = 0; it < 8; ++it) {
        size_t e = (size_t)cta * 8192 + (size_t)it * 1024 + (size_t)tid * 4;
        float4 v = *(const float4*)(X0 + e);
        float xs[4] = {v.x, v.y, v.z, v.w};
#pragma unroll
        for (int j = 0; j < 4; ++j) {
            __nv_bfloat16 h = __float2bfloat16(xs[j]);
            g_Xhi[e + j] = h;
            g_Xlo[e + j] = __float2bfloat16(xs[j] - __bfloat162float(h));
        }
    }
}

// ---------------------------------------------------------------------------
// zgemm: z_k[b,j] = sum_d x[b,d]*B^k[j,d], bf16 split-3 mma.sync (proven).
// CTA 128x128xK256, 8 warps, warp tile 64x32, double-buffered cp.async.
// grid (32, 2, NPOW), 256 threads.
// ---------------------------------------------------------------------------
#define TB_XHI 0
#define TB_XLO 16384
#define TB_MHI 32768
#define TB_MLO 49152
#define BUFSZ  65536
#define SMEM_Z (2 * BUFSZ)   // 128 KB dynamic

__global__ void __launch_bounds__(256)
zgemm_kernel()
{
    extern __shared__ char dsm[];
    const u32 sb = smem_u32(dsm);
    const int tid = threadIdx.x;
    const int lane = tid & 31;
    const int wid = tid >> 5;
    const int kz = blockIdx.z;                 // power index (k = kz+1)
    const int bBase = blockIdx.x * 128;
    const int nBase = blockIdx.y * 128;

    const __nv_bfloat16* __restrict__ xh = g_Xhi + (size_t)bBase * D;
    const __nv_bfloat16* __restrict__ xl = g_Xlo + (size_t)bBase * D;
    const __nv_bfloat16* __restrict__ mh = g_Whi + (size_t)kz * DD + (size_t)nBase * D;
    const __nv_bfloat16* __restrict__ ml = g_Wlo + (size_t)kz * DD + (size_t)nBase * D;
    float* __restrict__ zout = g_Z + (size_t)kz * (BATCH * D);

    const int wm = (wid & 1) * 64;
    const int wn = (wid >> 1) * 32;
    const int aRow  = wm + (lane & 15);
    const u32 aColB = (u32)(((lane >> 4) * 8) * 2);
    const int bRow  = wn + ((lane >> 4) << 3) + (lane & 7);
    const u32 bColB = (u32)((((lane >> 3) & 1) * 8) * 2);

    float acc[4][4][4];
#pragma unroll
    for (int mi = 0; mi < 4; ++mi)
#pragma unroll
        for (int nf = 0; nf < 4; ++nf)
#pragma unroll
            for (int r = 0; r < 4; ++r) acc[mi][nf][r] = 0.0f;

    auto load_chunk = [&](int buf, int cd) {
        u32 sbuf = sb + (u32)buf * BUFSZ;
#pragma unroll
        for (int it = 0; it < 4; ++it) {
            int v = tid + it * 256;
            int r = v >> 3, j = v & 7;
            u32 off = SWZ((u32)(r * 128 + j * 16));
            size_t g = (size_t)r * D + cd + j * 8;
            cpa16(sbuf + TB_XHI + off, xh + g);
            cpa16(sbuf + TB_XLO + off, xl + g);
            cpa16(sbuf + TB_MHI + off, mh + g);
            cpa16(sbuf + TB_MLO + off, ml + g);
        }
        cpa_commit();
    };

    load_chunk(0, 0);

    for (int c = 0; c < 4; ++c) {
        if (c < 3) { load_chunk((c + 1) & 1, (c + 1) * 64); cpa_wait<1>(); }
        else       { cpa_wait<0>(); }
        __syncthreads();

        const u32 sbuf = sb + (u32)(c & 1) * BUFSZ;

#pragma unroll
        for (int k16 = 0; k16 < 4; ++k16) {
            const u32 kb = (u32)(k16 * 32);

            u32 bh[8], bl[8];
            {
                u32 o0 = SWZ((u32)(bRow * 128) + kb + bColB);
                u32 o1 = SWZ((u32)((bRow + 16) * 128) + kb + bColB);
                ldm4(bh,     sbuf + TB_MHI + o0);
                ldm4(bh + 4, sbuf + TB_MHI + o1);
                ldm4(bl,     sbuf + TB_MLO + o0);
                ldm4(bl + 4, sbuf + TB_MLO + o1);
            }

            u32 af[4][4];
#pragma unroll
            for (int mi = 0; mi < 4; ++mi) {
                u32 oa = SWZ((u32)((aRow + mi * 16) * 128) + kb + aColB);
                ldm4(af[mi], sbuf + TB_XHI + oa);
            }
#pragma unroll
            for (int mi = 0; mi < 4; ++mi)
#pragma unroll
                for (int nf = 0; nf < 4; ++nf) {
                    mma16816(acc[mi][nf], af[mi], bh[nf * 2], bh[nf * 2 + 1]);
                    mma16816(acc[mi][nf], af[mi], bl[nf * 2], bl[nf * 2 + 1]);
                }
#pragma unroll
            for (int mi = 0; mi < 4; ++mi) {
                u32 oa = SWZ((u32)((aRow + mi * 16) * 128) + kb + aColB);
                ldm4(af[mi], sbuf + TB_XLO + oa);
            }
#pragma unroll
            for (int mi = 0; mi < 4; ++mi)
#pragma unroll
                for (int nf = 0; nf < 4; ++nf)
                    mma16816(acc[mi][nf], af[mi], bh[nf * 2], bh[nf * 2 + 1]);
        }
        __syncthreads();
    }

    // epilogue: z[b, j]
    const int gr = lane >> 2;
    const int gc = (lane & 3) * 2;
#pragma unroll
    for (int mi = 0; mi < 4; ++mi) {
#pragma unroll
        for (int nf = 0; nf < 4; ++nf) {
            int r0 = bBase + wm + mi * 16 + gr;
            int c0 = nBase + wn + nf * 8 + gc;
            float2 v0; v0.x = acc[mi][nf][0]; v0.y = acc[mi][nf][1];
            float2 v1; v1.x = acc[mi][nf][2]; v1.y = acc[mi][nf][3];
            *(float2*)(zout + (size_t)r0 * D + c0) = v0;
            *(float2*)(zout + (size_t)(r0 + 8) * D + c0) = v1;
        }
    }
}

// ---------------------------------------------------------------------------
// combine: out[b,t,c] = e^{-s_t} * ( x[b,c] + sum_{k=1..NPOW} s_t^k/k! * z_k[b,c] ).
// Thread holds x + all z_k for its 8 cols in registers (packed f32x2),
// loops t, writes 2x16B per t. CTA = 32 b x 64 cols. grid (128, 4).
// ---------------------------------------------------------------------------
__global__ void __launch_bounds__(256)
combine_kernel(const float* __restrict__ X0, float* __restrict__ out)
{
    const int tid = threadIdx.x;
    const int cg = tid & 7;
    const int r  = tid >> 3;
    const int b  = blockIdx.x * 32 + r;
    const int c  = blockIdx.y * 64 + cg * 8;

    u64t zz[NPOW + 1][4];
    {
        const float* p = X0 + (size_t)b * D + c;
        ulonglong2 u0 = *(const ulonglong2*)(p);
        ulonglong2 u1 = *(const ulonglong2*)(p + 4);
        zz[0][0] = u0.x; zz[0][1] = u0.y; zz[0][2] = u1.x; zz[0][3] = u1.y;
    }
#pragma unroll
    for (int k = 1; k <= NPOW; ++k) {
        const float* p = g_Z + (size_t)(k - 1) * (BATCH * D) + (size_t)b * D + c;
        ulonglong2 u0 = *(const ulonglong2*)(p);
        ulonglong2 u1 = *(const ulonglong2*)(p + 4);
        zz[k][0] = u0.x; zz[k][1] = u0.y; zz[k][2] = u1.x; zz[k][3] = u1.y;
    }

    float* obase = out + (size_t)b * T * D + c;
    for (int t = 0; t < T; ++t) {
        float s = DT_STEP * (float)t;
        float ck = expf(-s);
        u64t w = pack_dup(ck);
        u64t a0 = mul2(w, zz[0][0]);
        u64t a1 = mul2(w, zz[0][1]);
        u64t a2 = mul2(w, zz[0][2]);
        u64t a3 = mul2(w, zz[0][3]);
#pragma unroll
        for (int k = 1; k <= NPOW; ++k) {
            ck *= s / (float)k;
            w = pack_dup(ck);
            fma2(a0, w, zz[k][0]);
            fma2(a1, w, zz[k][1]);
            fma2(a2, w, zz[k][2]);
            fma2(a3, w, zz[k][3]);
        }
        ulonglong2 v0; v0.x = a0; v0.y = a1;
        ulonglong2 v1; v1.x = a2; v1.y = a3;
        float* o = obase + (size_t)t * D;
        *(ulonglong2*)(o) = v0;
        *(ulonglong2*)(o + 4) = v1;
    }
}

// ---------------------------------------------------------------------------
// kernel_launch: memset (barrier reset) + 3 kernels; graph-capturable.
// ---------------------------------------------------------------------------
extern "C" void kernel_launch(void* const* d_in, const int* in_sizes, int n_in,
                              void* d_out, int out_size)
{
    const float* X0 = (const float*)d_in[0];   // [BATCH, D]
    const float* A  = (const float*)d_in[1];   // [D, D]
    if (n_in >= 2 && in_sizes[0] == DD && in_sizes[1] == BATCH * D) {
        const float* tmp = X0; X0 = A; A = tmp;  // defensive: metadata order swapped
    }
    float* out = (float*)d_out;

    void* cntAddr = nullptr;
    cudaGetSymbolAddress(&cntAddr, g_cnt);

    cudaFuncSetAttribute(zgemm_kernel,
                         cudaFuncAttributeMaxDynamicSharedMemorySize, SMEM_Z);

    // 0) reset grid-barrier counters (async, capturable)
    cudaMemsetAsync(cntAddr, 0, sizeof(u32) * 8, 0);

    // 1) persistent prep: B, power chain W2..W10, all bf16 splits
    prep_kernel<<<128, 256>>>(A, X0);

    // 2) z_k = x * (B^T)^k for k=1..NPOW — 10 GEMMs, one launch
    zgemm_kernel<<<dim3(BATCH / 128, D / 128, NPOW), 256, SMEM_Z>>>();

    // 3) Combine: weighted z-sum per (b, t), streamed to out
    combine_kernel<<<dim3(BATCH / 32, D / 64), 256>>>(X0, out);

    (void)n_in; (void)out_size;
}

// round 17
// speedup vs baseline: 1.0028x; 1.0028x over previous
#include <cuda_runtime.h>
#include <cuda_bf16.h>

// Problem constants
#define D        256
#define DD       65536
#define BATCH    4096
#define T        100
#define DT_STEP  0.05f
#define NPOW     10          // z_k terms k=1..10; tail ~5e-6 rel worst-case

typedef unsigned int u32;
typedef unsigned long long u64t;

// ---------------------------------------------------------------------------
// Device scratch (static globals; no allocation anywhere)
// ---------------------------------------------------------------------------
__device__ float          g_W[12ull * DD];              // B^k, k=1..10 (slot 0 unused)
__device__ __nv_bfloat16  g_Whi[(size_t)NPOW * DD];     // bf16 hi of B^k (slot k-1)
__device__ __nv_bfloat16  g_Wlo[(size_t)NPOW * DD];     // bf16 lo
__device__ __nv_bfloat16  g_Xhi[(size_t)BATCH * D];
__device__ __nv_bfloat16  g_Xlo[(size_t)BATCH * D];
__device__ float          g_Z[(size_t)NPOW * BATCH * D]; // z_k = x*(B^T)^k (slot k-1)
__device__ u32            g_cnt[8];                      // grid-barrier counters (memset per run)

// ---------------------------------------------------------------------------
// PTX helpers (baseline ISA only — compute_103-safe)
// ---------------------------------------------------------------------------
__device__ __forceinline__ u32 smem_u32(const void* p) {
    u32 a;
    asm("{ .reg .u64 t; cvta.to.shared.u64 t, %1; cvt.u32.u64 %0, t; }" : "=r"(a) : "l"(p));
    return a;
}
__device__ __forceinline__ void cpa16(u32 dst, const void* src) {
    asm volatile("cp.async.cg.shared.global [%0], [%1], 16;" :: "r"(dst), "l"(src) : "memory");
}
__device__ __forceinline__ void cpa_commit() { asm volatile("cp.async.commit_group;" ::: "memory"); }
template <int N>
__device__ __forceinline__ void cpa_wait() {
    asm volatile("cp.async.wait_group %0;" :: "n"(N) : "memory");
}
__device__ __forceinline__ void ldm4(u32* r, u32 a) {
    asm volatile("ldmatrix.sync.aligned.m8n8.x4.shared.b16 {%0,%1,%2,%3}, [%4];"
                 : "=r"(r[0]), "=r"(r[1]), "=r"(r[2]), "=r"(r[3]) : "r"(a));
}
__device__ __forceinline__ void mma16816(float* c, const u32* a, u32 b0, u32 b1) {
    asm volatile("mma.sync.aligned.m16n8k16.row.col.f32.bf16.bf16.f32 "
                 "{%0,%1,%2,%3}, {%4,%5,%6,%7}, {%8,%9}, {%0,%1,%2,%3};"
                 : "+f"(c[0]), "+f"(c[1]), "+f"(c[2]), "+f"(c[3])
                 : "r"(a[0]), "r"(a[1]), "r"(a[2]), "r"(a[3]), "r"(b0), "r"(b1));
}
__device__ __forceinline__ u64t pack_dup(float v) {
    u64t r;
    asm("mov.b64 %0, {%1, %1};" : "=l"(r) : "f"(v));
    return r;
}
__device__ __forceinline__ void fma2(u64t& d, u64t a, u64t b) {
    asm("fma.rn.f32x2 %0, %1, %2, %0;" : "+l"(d) : "l"(a), "l"(b));
}
__device__ __forceinline__ u64t mul2(u64t a, u64t b) {
    u64t r;
    asm("mul.rn.f32x2 %0, %1, %2;" : "=l"(r) : "l"(a), "l"(b));
    return r;
}
__device__ __forceinline__ void stcs2(void* p, u64t a, u64t b) {
    asm volatile("st.global.cs.v2.u64 [%0], {%1, %2};" :: "l"(p), "l"(a), "l"(b) : "memory");
}

#define SWZ64(o) ((o) ^ (((o) >> 3) & 0x30))

// ---------------------------------------------------------------------------
// Software grid barrier: monotonic counter per phase (idx), release+acquire.
// All 128 CTAs guaranteed co-resident (128 < 148 SMs).
// ---------------------------------------------------------------------------
__device__ __forceinline__ void gridbar(int idx, u32 n) {
    __syncthreads();
    if (threadIdx.x == 0) {
        __threadfence();                       // release prior stores GPU-wide
        atomicAdd(&g_cnt[idx], 1u);
        u32 v;
        do {
            asm volatile("ld.global.acquire.gpu.u32 %0, [%1];"
                         : "=r"(v) : "l"(&g_cnt[idx]) : "memory");
        } while (v < n);
    }
    __syncthreads();
}

// ---------------------------------------------------------------------------
// 32x32 tile of a 256x256x256 fp32 matmul: C_tile = X @ Y  (proven body)
// ---------------------------------------------------------------------------
__device__ void mm_tile(const float* __restrict__ X,
                        const float* __restrict__ Y,
                        float* __restrict__ C, int tileIdx)
{
    __shared__ float Xs[32][34];
    __shared__ float Ys[32][32];

    const int rowBase = (tileIdx >> 3) * 32;
    const int colBase = (tileIdx & 7) * 32;

    const int tid = threadIdx.x;
    const int lrow = tid >> 3;
    const int lq   = (tid & 7) * 4;
    const int tx = tid & 15;
    const int ty = tid >> 4;

    const float* xPtr = X + (size_t)(rowBase + lrow) * D + lq;
    const float* yPtr = Y + (size_t)lrow * D + colBase + lq;

    float4 xv = *(const float4*)xPtr;
    float4 yv = *(const float4*)yPtr;

    float a00 = 0.f, a01 = 0.f, a10 = 0.f, a11 = 0.f;

    for (int d0 = 0; d0 < D; d0 += 32) {
        __syncthreads();
        Xs[lq + 0][lrow] = xv.x; Xs[lq + 1][lrow] = xv.y;
        Xs[lq + 2][lrow] = xv.z; Xs[lq + 3][lrow] = xv.w;
        *(float4*)&Ys[lrow][lq] = yv;
        __syncthreads();

        if (d0 + 32 < D) {
            xv = *(const float4*)(xPtr + d0 + 32);
            yv = *(const float4*)(yPtr + (size_t)(d0 + 32) * D);
        }

#pragma unroll
        for (int kk = 0; kk < 32; ++kk) {
            float2 a = *(const float2*)&Xs[kk][ty * 2];
            float2 b = *(const float2*)&Ys[kk][tx * 2];
            a00 += a.x * b.x; a01 += a.x * b.y;
            a10 += a.y * b.x; a11 += a.y * b.y;
        }
    }

    int gr = rowBase + ty * 2;
    int gc = colBase + tx * 2;
    float2 v0; v0.x = a00; v0.y = a01;
    float2 v1; v1.x = a10; v1.y = a11;
    *(float2*)&C[(size_t)gr * D + gc] = v0;
    *(float2*)&C[(size_t)(gr + 1) * D + gc] = v1;
}

// ---------------------------------------------------------------------------
// prep: ONE persistent kernel (128 CTAs) = B build + power chain + splits.
//   ph0: W1 = B = A + I
//   ph1: W2 = W1*W1 (CTAs 0-63) ; X0 bf16 split (CTAs 64-127)
//   ph2: W3 = W2*W1 ; W4 = W2*W2
//   ph3: W5..W8 = W4*{W1..W4} (2 tiles/CTA)
//   ph4: W9 = W8*W1 ; W10 = W8*W2
//   ph5: bf16 hi/lo splits of W1..W10
// ---------------------------------------------------------------------------
#define WPD(k) (g_W + (size_t)(k) * DD)

__global__ void __launch_bounds__(256)
prep_kernel(const float* __restrict__ A, const float* __restrict__ X0)
{
    const int tid = threadIdx.x;
    const int cta = blockIdx.x;

    // ---- phase 0: B = A + I ----
#pragma unroll
    for (int j = 0; j < 2; ++j) {
        int e = cta * 512 + j * 256 + tid;
        int r = e >> 8, c = e & 255;
        g_W[DD + e] = A[e] + ((r == c) ? 1.0f : 0.0f);
    }
    gridbar(0, 128);

    // ---- phase 1: W2 on half the CTAs, X-split on the other half ----
    if (cta < 64) {
        mm_tile(WPD(1), WPD(1), WPD(2), cta);
    } else {
        int cb = cta - 64;   // 0..63, each handles 16384 floats of X
#pragma unroll
        for (int it = 0; it < 16; ++it) {
            size_t e = (size_t)cb * 16384 + (size_t)it * 1024 + (size_t)tid * 4;
            float4 v = *(const float4*)(X0 + e);
            float xs[4] = {v.x, v.y, v.z, v.w};
#pragma unroll
            for (int j = 0; j < 4; ++j) {
                __nv_bfloat16 h = __float2bfloat16(xs[j]);
                g_Xhi[e + j] = h;
                g_Xlo[e + j] = __float2bfloat16(xs[j] - __bfloat162float(h));
            }
        }
    }
    gridbar(1, 128);

    // ---- phase 2 ----
    if (cta < 64) mm_tile(WPD(2), WPD(1), WPD(3), cta);
    else          mm_tile(WPD(2), WPD(2), WPD(4), cta - 64);
    gridbar(2, 128);

    // ---- phase 3: 256 tiles, 2 per CTA ----
#pragma unroll
    for (int q = 0; q < 2; ++q) {
        int tt = cta * 2 + q;          // 0..255
        int m = tt >> 6;               // 0..3
        mm_tile(WPD(4), WPD(1 + m), WPD(5 + m), tt & 63);
    }
    gridbar(3, 128);

    // ---- phase 4 ----
    if (cta < 64) mm_tile(WPD(8), WPD(1), WPD(9), cta);
    else          mm_tile(WPD(8), WPD(2), WPD(10), cta - 64);
    gridbar(4, 128);

    // ---- phase 5: W1..W10 -> bf16 hi/lo (NPOW*DD = 655360 floats) ----
#pragma unroll
    for (int it = 0; it < 5; ++it) {
        size_t e = (size_t)cta * 5120 + (size_t)it * 1024 + (size_t)tid * 4;
        float4 v = *(const float4*)(g_W + DD + e);
        float xs[4] = {v.x, v.y, v.z, v.w};
#pragma unroll
        for (int j = 0; j < 4; ++j) {
            __nv_bfloat16 h = __float2bfloat16(xs[j]);
            g_Whi[e + j] = h;
            g_Wlo[e + j] = __float2bfloat16(xs[j] - __bfloat162float(h));
        }
    }
}

// ---------------------------------------------------------------------------
// zgemm: z_k[b,j] = sum_d x[b,d]*B^k[j,d], bf16 split-3 mma.sync.
// CTA 128x128, K in 8 chunks of 32 (64B swizzled rows, SW64), double-buffered
// 32KB stages -> 64KB smem -> 2 CTAs/SM (4 warps/SMSP for latency hiding).
// grid (32, 2, NPOW), 256 threads.
// ---------------------------------------------------------------------------
#define TBX_HI 0
#define TBX_LO 8192
#define TBM_HI 16384
#define TBM_LO 24576
#define STAGE  32768
#define SMEM_Z (2 * STAGE)   // 64 KB dynamic

__global__ void __launch_bounds__(256, 2)
zgemm_kernel()
{
    extern __shared__ char dsm[];
    const u32 sb = smem_u32(dsm);
    const int tid = threadIdx.x;
    const int lane = tid & 31;
    const int wid = tid >> 5;
    const int kz = blockIdx.z;                 // power index (k = kz+1)
    const int bBase = blockIdx.x * 128;
    const int nBase = blockIdx.y * 128;

    const __nv_bfloat16* __restrict__ xh = g_Xhi + (size_t)bBase * D;
    const __nv_bfloat16* __restrict__ xl = g_Xlo + (size_t)bBase * D;
    const __nv_bfloat16* __restrict__ mh = g_Whi + (size_t)kz * DD + (size_t)nBase * D;
    const __nv_bfloat16* __restrict__ ml = g_Wlo + (size_t)kz * DD + (size_t)nBase * D;
    float* __restrict__ zout = g_Z + (size_t)kz * (BATCH * D);

    const int wm = (wid & 1) * 64;
    const int wn = (wid >> 1) * 32;
    const int aRow  = wm + (lane & 15);
    const u32 aColB = (u32)((lane >> 4) * 16);
    const int bRow  = wn + ((lane >> 4) << 3) + (lane & 7);
    const u32 bColB = (u32)(((lane >> 3) & 1) * 16);

    float acc[4][4][4];
#pragma unroll
    for (int mi = 0; mi < 4; ++mi)
#pragma unroll
        for (int nf = 0; nf < 4; ++nf)
#pragma unroll
            for (int r = 0; r < 4; ++r) acc[mi][nf][r] = 0.0f;

    // loader: 4 tiles x 128 rows x 64B, swizzled; 8 cpa16 per thread
    auto load_chunk = [&](int buf, int cd) {
        u32 sbuf = sb + (u32)buf * STAGE;
#pragma unroll
        for (int it = 0; it < 2; ++it) {
            int v = tid + it * 256;           // 0..511
            int r = v >> 2, j = v & 3;
            u32 off = SWZ64((u32)(r * 64 + j * 16));
            size_t g = (size_t)r * D + cd + j * 8;
            cpa16(sbuf + TBX_HI + off, xh + g);
            cpa16(sbuf + TBX_LO + off, xl + g);
            cpa16(sbuf + TBM_HI + off, mh + g);
            cpa16(sbuf + TBM_LO + off, ml + g);
        }
        cpa_commit();
    };

    load_chunk(0, 0);

    for (int c = 0; c < 8; ++c) {
        if (c < 7) { load_chunk((c + 1) & 1, (c + 1) * 32); cpa_wait<1>(); }
        else       { cpa_wait<0>(); }
        __syncthreads();

        const u32 sbuf = sb + (u32)(c & 1) * STAGE;

#pragma unroll
        for (int k16 = 0; k16 < 2; ++k16) {
            const u32 kb = (u32)(k16 * 32);

            u32 bh[8], bl[8];
            {
                u32 o0 = SWZ64((u32)(bRow * 64) + kb + bColB);
                u32 o1 = SWZ64((u32)((bRow + 16) * 64) + kb + bColB);
                ldm4(bh,     sbuf + TBM_HI + o0);
                ldm4(bh + 4, sbuf + TBM_HI + o1);
                ldm4(bl,     sbuf + TBM_LO + o0);
                ldm4(bl + 4, sbuf + TBM_LO + o1);
            }

            u32 af[4][4];
#pragma unroll
            for (int mi = 0; mi < 4; ++mi) {
                u32 oa = SWZ64((u32)((aRow + mi * 16) * 64) + kb + aColB);
                ldm4(af[mi], sbuf + TBX_HI + oa);
            }
#pragma unroll
            for (int mi = 0; mi < 4; ++mi)
#pragma unroll
                for (int nf = 0; nf < 4; ++nf) {
                    mma16816(acc[mi][nf], af[mi], bh[nf * 2], bh[nf * 2 + 1]);
                    mma16816(acc[mi][nf], af[mi], bl[nf * 2], bl[nf * 2 + 1]);
                }
#pragma unroll
            for (int mi = 0; mi < 4; ++mi) {
                u32 oa = SWZ64((u32)((aRow + mi * 16) * 64) + kb + aColB);
                ldm4(af[mi], sbuf + TBX_LO + oa);
            }
#pragma unroll
            for (int mi = 0; mi < 4; ++mi)
#pragma unroll
                for (int nf = 0; nf < 4; ++nf)
                    mma16816(acc[mi][nf], af[mi], bh[nf * 2], bh[nf * 2 + 1]);
        }
        __syncthreads();
    }

    // epilogue: z[b, j]
    const int gr = lane >> 2;
    const int gc = (lane & 3) * 2;
#pragma unroll
    for (int mi = 0; mi < 4; ++mi) {
#pragma unroll
        for (int nf = 0; nf < 4; ++nf) {
            int r0 = bBase + wm + mi * 16 + gr;
            int c0 = nBase + wn + nf * 8 + gc;
            float2 v0; v0.x = acc[mi][nf][0]; v0.y = acc[mi][nf][1];
            float2 v1; v1.x = acc[mi][nf][2]; v1.y = acc[mi][nf][3];
            *(float2*)(zout + (size_t)r0 * D + c0) = v0;
            *(float2*)(zout + (size_t)(r0 + 8) * D + c0) = v1;
        }
    }
}

// ---------------------------------------------------------------------------
// combine: out[b,t,c] = sum_{k=0..NPOW} w[t][k] * z_k[b,c], z_0 = x.
// Packed f32x2 weight table in smem (built once per CTA); t-loop is
// 11 broadcast LDS.64 + 44 fma2 + 2 streaming 16B stores.
// CTA = 32 b x 64 cols. grid (128, 4).
// ---------------------------------------------------------------------------
__global__ void __launch_bounds__(256)
combine_kernel(const float* __restrict__ X0, float* __restrict__ out)
{
    __shared__ u64t wtab[T][12];

    const int tid = threadIdx.x;
    if (tid < T) {
        float s = DT_STEP * (float)tid;
        float ck = expf(-s);
        wtab[tid][0] = pack_dup(ck);
#pragma unroll
        for (int k = 1; k <= NPOW; ++k) {
            ck *= s / (float)k;
            wtab[tid][k] = pack_dup(ck);
        }
    }

    const int cg = tid & 7;
    const int r  = tid >> 3;
    const int b  = blockIdx.x * 32 + r;
    const int c  = blockIdx.y * 64 + cg * 8;

    u64t zz[NPOW + 1][4];
    {
        const float* p = X0 + (size_t)b * D + c;
        ulonglong2 u0 = *(const ulonglong2*)(p);
        ulonglong2 u1 = *(const ulonglong2*)(p + 4);
        zz[0][0] = u0.x; zz[0][1] = u0.y; zz[0][2] = u1.x; zz[0][3] = u1.y;
    }
#pragma unroll
    for (int k = 1; k <= NPOW; ++k) {
        const float* p = g_Z + (size_t)(k - 1) * (BATCH * D) + (size_t)b * D + c;
        ulonglong2 u0 = *(const ulonglong2*)(p);
        ulonglong2 u1 = *(const ulonglong2*)(p + 4);
        zz[k][0] = u0.x; zz[k][1] = u0.y; zz[k][2] = u1.x; zz[k][3] = u1.y;
    }
    __syncthreads();

    float* obase = out + (size_t)b * T * D + c;
    for (int t = 0; t < T; ++t) {
        u64t w = wtab[t][0];
        u64t a0 = mul2(w, zz[0][0]);
        u64t a1 = mul2(w, zz[0][1]);
        u64t a2 = mul2(w, zz[0][2]);
        u64t a3 = mul2(w, zz[0][3]);
#pragma unroll
        for (int k = 1; k <= NPOW; ++k) {
            w = wtab[t][k];
            fma2(a0, w, zz[k][0]);
            fma2(a1, w, zz[k][1]);
            fma2(a2, w, zz[k][2]);
            fma2(a3, w, zz[k][3]);
        }
        float* o = obase + (size_t)t * D;
        stcs2(o,     a0, a1);
        stcs2(o + 4, a2, a3);
    }
}

// ---------------------------------------------------------------------------
// kernel_launch: memset (barrier reset) + 3 kernels; graph-capturable.
// ---------------------------------------------------------------------------
extern "C" void kernel_launch(void* const* d_in, const int* in_sizes, int n_in,
                              void* d_out, int out_size)
{
    const float* X0 = (const float*)d_in[0];   // [BATCH, D]
    const float* A  = (const float*)d_in[1];   // [D, D]
    if (n_in >= 2 && in_sizes[0] == DD && in_sizes[1] == BATCH * D) {
        const float* tmp = X0; X0 = A; A = tmp;  // defensive: metadata order swapped
    }
    float* out = (float*)d_out;

    void* cntAddr = nullptr;
    cudaGetSymbolAddress(&cntAddr, g_cnt);

    cudaFuncSetAttribute(zgemm_kernel,
                         cudaFuncAttributeMaxDynamicSharedMemorySize, SMEM_Z);

    // 0) reset grid-barrier counters (async, capturable)
    cudaMemsetAsync(cntAddr, 0, sizeof(u32) * 8, 0);

    // 1) persistent prep: B, power chain W2..W10, all bf16 splits
    prep_kernel<<<128, 256>>>(A, X0);

    // 2) z_k = x * (B^T)^k for k=1..NPOW — 10 GEMMs, one launch
    zgemm_kernel<<<dim3(BATCH / 128, D / 128, NPOW), 256, SMEM_Z>>>();

    // 3) Combine: weighted z-sum per (b, t), streamed to out
    combine_kernel<<<dim3(BATCH / 32, D / 64), 256>>>(X0, out);

    (void)n_in; (void)out_size;
}